// round 1
// baseline (speedup 1.0000x reference)
#include <cuda_runtime.h>

#define HEADS 8
#define DIM_HEAD 64
#define NB 4
#define NC 512
#define NL 2048
#define HD (HEADS * DIM_HEAD)   /* 512  */
#define F3 (3 * HD)             /* 1536 */

// Scratch (no allocations allowed -> device globals)
__device__ float g_qkv[(size_t)NB * F3 * NL];   // 48 MB  qkv[b][f][l]
__device__ float g_attn[(size_t)NB * HD * NL];  // 16 MB  attn-out[b][h*64+d][l]

// ---------------------------------------------------------------------------
// GEMM: Y[b][m][n] = sum_k W[k][m] * X[b][k][n]  (+ bias[m])
// W row-major [K, M]; X [B, K, N]; Y [B, M, N]. All dims multiples of tile.
// 256 threads, 64x64 block tile, K-tile 16, 4x4 register micro-tile.
// ---------------------------------------------------------------------------
__global__ __launch_bounds__(256) void gemm_wt_x(
    const float* __restrict__ W, const float* __restrict__ X,
    float* __restrict__ Y, const float* __restrict__ bias,
    int M, int N, int K)
{
    __shared__ float Ws[16][64];
    __shared__ float Xs[16][64];

    const int b  = blockIdx.z;
    const float* Xb = X + (size_t)b * K * N;
    float*       Yb = Y + (size_t)b * M * N;

    const int m0 = blockIdx.y * 64;
    const int n0 = blockIdx.x * 64;
    const int tid = threadIdx.x;
    const int tx = tid & 15;
    const int ty = tid >> 4;

    float acc[4][4];
#pragma unroll
    for (int i = 0; i < 4; i++)
#pragma unroll
        for (int j = 0; j < 4; j++) acc[i][j] = 0.f;

    for (int k0 = 0; k0 < K; k0 += 16) {
#pragma unroll
        for (int r = 0; r < 4; r++) {
            int idx = tid + r * 256;       // 0..1023
            int kk  = idx >> 6;
            int col = idx & 63;
            Ws[kk][col] = W[(size_t)(k0 + kk) * M + m0 + col];
            Xs[kk][col] = Xb[(size_t)(k0 + kk) * N + n0 + col];
        }
        __syncthreads();
#pragma unroll
        for (int kk = 0; kk < 16; kk++) {
            float a[4], x[4];
#pragma unroll
            for (int i = 0; i < 4; i++) a[i] = Ws[kk][ty + 16 * i];
#pragma unroll
            for (int j = 0; j < 4; j++) x[j] = Xs[kk][tx + 16 * j];
#pragma unroll
            for (int i = 0; i < 4; i++)
#pragma unroll
                for (int j = 0; j < 4; j++) acc[i][j] += a[i] * x[j];
        }
        __syncthreads();
    }

#pragma unroll
    for (int i = 0; i < 4; i++) {
        int m = m0 + ty + 16 * i;
        float bv = bias ? bias[m] : 0.f;
#pragma unroll
        for (int j = 0; j < 4; j++) {
            int n = n0 + tx + 16 * j;
            Yb[(size_t)m * N + n] = acc[i][j] + bv;
        }
    }
}

// ---------------------------------------------------------------------------
// Flash attention, fp32. One CTA = one (b, h, 64-query tile).
// qkv layout: g_qkv[b][f][l] with q at f = h*64 + d, k at 512 + h*64 + d,
// v at 1024 + h*64 + d. l contiguous.
// 256 threads (16x16). Dynamic smem: Qs, Ks, Vs, Ps each [64][65].
// ---------------------------------------------------------------------------
__global__ __launch_bounds__(256) void attn_kernel(float* __restrict__ out)
{
    extern __shared__ float sm[];
    float* Qs = sm;
    float* Ks = sm + 64 * 65;
    float* Vs = sm + 2 * 64 * 65;
    float* Ps = sm + 3 * 64 * 65;

    const int bh = blockIdx.y;       // 0..31
    const int b  = bh >> 3;
    const int h  = bh & 7;
    const int i0 = blockIdx.x * 64;

    const float* qb = g_qkv + (size_t)b * F3 * NL + (size_t)(h * DIM_HEAD) * NL;
    const float* kb = qb + (size_t)HD * NL;
    const float* vb = qb + (size_t)(2 * HD) * NL;

    const int tid = threadIdx.x;
    const int tx  = tid & 15;
    const int ty  = tid >> 4;
    const float scale = 0.125f;      // 64^-0.5

    // Load Q tile (scaled): Qs[d][i]
    for (int idx = tid; idx < 64 * 64; idx += 256) {
        int d = idx >> 6, i = idx & 63;
        Qs[d * 65 + i] = qb[(size_t)d * NL + i0 + i] * scale;
    }

    float m_i[4], l_i[4], acc[4][4];
#pragma unroll
    for (int i = 0; i < 4; i++) {
        m_i[i] = -1e30f;
        l_i[i] = 0.f;
#pragma unroll
        for (int d = 0; d < 4; d++) acc[i][d] = 0.f;
    }

    for (int jt = 0; jt < NL / 64; jt++) {
        const int j0 = jt * 64;
        __syncthreads();   // prior PV / Q load consumers done before K/V overwrite
        for (int idx = tid; idx < 64 * 64; idx += 256) {
            int d = idx >> 6, j = idx & 63;
            Ks[d * 65 + j] = kb[(size_t)d * NL + j0 + j];
            Vs[d * 65 + j] = vb[(size_t)d * NL + j0 + j];
        }
        __syncthreads();

        // S[i][j] = sum_d Qs[d][i] * Ks[d][j]
        float s[4][4];
#pragma unroll
        for (int i = 0; i < 4; i++)
#pragma unroll
            for (int j = 0; j < 4; j++) s[i][j] = 0.f;

#pragma unroll 8
        for (int d = 0; d < 64; d++) {
            float qv[4], kv[4];
#pragma unroll
            for (int i = 0; i < 4; i++) qv[i] = Qs[d * 65 + ty + 16 * i];
#pragma unroll
            for (int j = 0; j < 4; j++) kv[j] = Ks[d * 65 + tx + 16 * j];
#pragma unroll
            for (int i = 0; i < 4; i++)
#pragma unroll
                for (int j = 0; j < 4; j++) s[i][j] += qv[i] * kv[j];
        }

        // Online softmax update per row (row i owned by the 16 lanes of one ty group)
#pragma unroll
        for (int i = 0; i < 4; i++) {
            float rm = s[i][0];
#pragma unroll
            for (int j = 1; j < 4; j++) rm = fmaxf(rm, s[i][j]);
#pragma unroll
            for (int off = 8; off > 0; off >>= 1)
                rm = fmaxf(rm, __shfl_xor_sync(0xffffffffu, rm, off, 16));

            float mnew = fmaxf(m_i[i], rm);
            float corr = __expf(m_i[i] - mnew);
            m_i[i] = mnew;

            float rs = 0.f;
#pragma unroll
            for (int j = 0; j < 4; j++) {
                float p = __expf(s[i][j] - mnew);
                s[i][j] = p;
                rs += p;
            }
#pragma unroll
            for (int off = 8; off > 0; off >>= 1)
                rs += __shfl_xor_sync(0xffffffffu, rs, off, 16);

            l_i[i] = l_i[i] * corr + rs;
#pragma unroll
            for (int d = 0; d < 4; d++) acc[i][d] *= corr;
        }

        // Stage P to shared: Ps[i][j]
#pragma unroll
        for (int i = 0; i < 4; i++)
#pragma unroll
            for (int j = 0; j < 4; j++)
                Ps[(ty + 16 * i) * 65 + tx + 16 * j] = s[i][j];
        __syncthreads();

        // O[i][d] += sum_j P[i][j] * V[d][j]
#pragma unroll 8
        for (int j = 0; j < 64; j++) {
            float pv[4], vv[4];
#pragma unroll
            for (int i = 0; i < 4; i++) pv[i] = Ps[(ty + 16 * i) * 65 + j];
#pragma unroll
            for (int d = 0; d < 4; d++) vv[d] = Vs[(tx + 16 * d) * 65 + j];
#pragma unroll
            for (int i = 0; i < 4; i++)
#pragma unroll
                for (int d = 0; d < 4; d++) acc[i][d] += pv[i] * vv[d];
        }
    }

    // Normalize, stage transposed (Ps[d][i]), coalesced write
    __syncthreads();
#pragma unroll
    for (int i = 0; i < 4; i++) {
        float inv = 1.f / l_i[i];
#pragma unroll
        for (int d = 0; d < 4; d++)
            Ps[(tx + 16 * d) * 65 + (ty + 16 * i)] = acc[i][d] * inv;
    }
    __syncthreads();

    float* ob = out + (size_t)b * HD * NL + (size_t)(h * DIM_HEAD) * NL;
    for (int idx = tid; idx < 64 * 64; idx += 256) {
        int d = idx >> 6, i = idx & 63;
        ob[(size_t)d * NL + i0 + i] = Ps[d * 65 + i];
    }
}

// ---------------------------------------------------------------------------
// Launch
// ---------------------------------------------------------------------------
extern "C" void kernel_launch(void* const* d_in, const int* in_sizes, int n_in,
                              void* d_out, int out_size)
{
    const float* x     = (const float*)d_in[0];   // [4, 512, 2048]
    const float* w_qkv = (const float*)d_in[1];   // [512, 1536]
    const float* w_out = (const float*)d_in[2];   // [512, 512]
    const float* b_out = (const float*)d_in[3];   // [512]
    float* y = (float*)d_out;                     // [4, 512, 2048]

    float* qkv;  cudaGetSymbolAddress((void**)&qkv,  g_qkv);
    float* attn; cudaGetSymbolAddress((void**)&attn, g_attn);

    // 1) QKV projection: M=1536, N=2048, K=512
    {
        dim3 grid(NL / 64, F3 / 64, NB);
        gemm_wt_x<<<grid, 256>>>(w_qkv, x, qkv, nullptr, F3, NL, NC);
    }

    // 2) Flash attention
    {
        const int smem = 4 * 64 * 65 * (int)sizeof(float);  // 66560 B
        cudaFuncSetAttribute(attn_kernel,
                             cudaFuncAttributeMaxDynamicSharedMemorySize, smem);
        dim3 grid(NL / 64, NB * HEADS);
        attn_kernel<<<grid, 256, smem>>>(attn);
    }

    // 3) Output projection + bias: M=512, N=2048, K=512
    {
        dim3 grid(NL / 64, HD / 64, NB);
        gemm_wt_x<<<grid, 256>>>(w_out, attn, y, b_out, NC, NL, HD);
    }
}

// round 2
// speedup vs baseline: 5.8674x; 5.8674x over previous
#include <cuda_runtime.h>
#include <cstdint>

#define HEADS 8
#define DIM_HEAD 64
#define NB 4
#define NC 512
#define NL 2048
#define HD (HEADS * DIM_HEAD)   /* 512  */
#define F3 (3 * HD)             /* 1536 */

// Scratch (no allocations allowed -> device globals)
__device__ float g_qkv[(size_t)NB * F3 * NL];   // 48 MB  qkv[b][f][l]
__device__ float g_attn[(size_t)NB * HD * NL];  // 16 MB  attn-out[b][h*64+d][l]

__device__ __forceinline__ uint32_t f2tf32(float f) {
    uint32_t u;
    asm("cvt.rna.tf32.f32 %0, %1;" : "=r"(u) : "f"(f));
    return u;
}

__device__ __forceinline__ void mma_tf32(float d[4],
                                         uint32_t a0, uint32_t a1, uint32_t a2, uint32_t a3,
                                         uint32_t b0, uint32_t b1) {
    asm volatile(
        "mma.sync.aligned.m16n8k8.row.col.f32.tf32.tf32.f32 "
        "{%0,%1,%2,%3}, {%4,%5,%6,%7}, {%8,%9}, {%0,%1,%2,%3};"
        : "+f"(d[0]), "+f"(d[1]), "+f"(d[2]), "+f"(d[3])
        : "r"(a0), "r"(a1), "r"(a2), "r"(a3), "r"(b0), "r"(b1));
}

// ---------------------------------------------------------------------------
// GEMM: Y[b][m][n] = sum_k W[k][m] * X[b][k][n]  (+ bias[m])
// tf32 mma. CTA tile 128x128, BK=16, 8 warps (4m x 2n), warp tile 32x64.
// ---------------------------------------------------------------------------
#define GPAD 136
__global__ __launch_bounds__(256) void gemm_tf32(
    const float* __restrict__ W, const float* __restrict__ X,
    float* __restrict__ Y, const float* __restrict__ bias,
    int M, int N, int K)
{
    __shared__ uint32_t As[16 * GPAD];
    __shared__ uint32_t Bs[16 * GPAD];

    const int b  = blockIdx.z;
    const float* Xb = X + (size_t)b * K * N;
    float*       Yb = Y + (size_t)b * M * N;

    const int m0 = blockIdx.y * 128;
    const int n0 = blockIdx.x * 128;
    const int tid  = threadIdx.x;
    const int warp = tid >> 5;
    const int lane = tid & 31;
    const int row  = lane >> 2;   // 0..7
    const int colk = lane & 3;    // 0..3
    const int wm = (warp >> 1) * 32;
    const int wn = (warp & 1) * 64;

    float acc[2][8][4];
#pragma unroll
    for (int i = 0; i < 2; i++)
#pragma unroll
        for (int j = 0; j < 8; j++)
#pragma unroll
            for (int c = 0; c < 4; c++) acc[i][j][c] = 0.f;

    for (int k0 = 0; k0 < K; k0 += 16) {
#pragma unroll
        for (int r = 0; r < 2; r++) {
            int v  = tid + r * 256;       // 0..511
            int kk = v >> 5;              // 0..15
            int c4 = (v & 31) * 4;        // 0..124
            float4 w4 = *(const float4*)(W  + (size_t)(k0 + kk) * M + m0 + c4);
            As[kk * GPAD + c4 + 0] = f2tf32(w4.x);
            As[kk * GPAD + c4 + 1] = f2tf32(w4.y);
            As[kk * GPAD + c4 + 2] = f2tf32(w4.z);
            As[kk * GPAD + c4 + 3] = f2tf32(w4.w);
            float4 x4 = *(const float4*)(Xb + (size_t)(k0 + kk) * N + n0 + c4);
            Bs[kk * GPAD + c4 + 0] = f2tf32(x4.x);
            Bs[kk * GPAD + c4 + 1] = f2tf32(x4.y);
            Bs[kk * GPAD + c4 + 2] = f2tf32(x4.z);
            Bs[kk * GPAD + c4 + 3] = f2tf32(x4.w);
        }
        __syncthreads();

#pragma unroll
        for (int ks = 0; ks < 2; ks++) {
            const int kb = ks * 8 + colk;
            uint32_t a[2][4];
#pragma unroll
            for (int i = 0; i < 2; i++) {
                a[i][0] = As[kb * GPAD + wm + i * 16 + row];
                a[i][1] = As[kb * GPAD + wm + i * 16 + row + 8];
                a[i][2] = As[(kb + 4) * GPAD + wm + i * 16 + row];
                a[i][3] = As[(kb + 4) * GPAD + wm + i * 16 + row + 8];
            }
#pragma unroll
            for (int j = 0; j < 8; j++) {
                uint32_t b0 = Bs[kb * GPAD + wn + j * 8 + row];
                uint32_t b1 = Bs[(kb + 4) * GPAD + wn + j * 8 + row];
#pragma unroll
                for (int i = 0; i < 2; i++)
                    mma_tf32(acc[i][j], a[i][0], a[i][1], a[i][2], a[i][3], b0, b1);
            }
        }
        __syncthreads();
    }

#pragma unroll
    for (int i = 0; i < 2; i++) {
        int m = m0 + wm + i * 16 + row;
        float bv0 = bias ? bias[m]     : 0.f;
        float bv1 = bias ? bias[m + 8] : 0.f;
#pragma unroll
        for (int j = 0; j < 8; j++) {
            int n = n0 + wn + j * 8 + colk * 2;
            Yb[(size_t)m * N + n]           = acc[i][j][0] + bv0;
            Yb[(size_t)m * N + n + 1]       = acc[i][j][1] + bv0;
            Yb[(size_t)(m + 8) * N + n]     = acc[i][j][2] + bv1;
            Yb[(size_t)(m + 8) * N + n + 1] = acc[i][j][3] + bv1;
        }
    }
}

// ---------------------------------------------------------------------------
// Flash attention, tf32 mma. One CTA = (b, h, 64-query tile), 128 threads.
// Warp w owns query rows [16w, 16w+16). 64-key tiles, online softmax in
// mma fragments. Smem (tf32 bits): Qs[64][72], Ks[64][72], Vs[64][68], Ps[64][68].
// ---------------------------------------------------------------------------
#define QK_PAD 72
#define PV_PAD 68
__global__ __launch_bounds__(128) void attn_tf32(float* __restrict__ out)
{
    extern __shared__ uint32_t sm[];
    uint32_t* Qs = sm;                       // [64][72]
    uint32_t* Ks = Qs + 64 * QK_PAD;         // [64][72]
    uint32_t* Vs = Ks + 64 * QK_PAD;         // [64][68]
    uint32_t* Ps = Vs + 64 * PV_PAD;         // [64][68]

    const int bh = blockIdx.y;
    const int b  = bh >> 3;
    const int h  = bh & 7;
    const int i0 = blockIdx.x * 64;

    const float* qb = g_qkv + (size_t)b * F3 * NL + (size_t)(h * DIM_HEAD) * NL;
    const float* kb = qb + (size_t)HD * NL;
    const float* vb = qb + (size_t)(2 * HD) * NL;

    const int tid  = threadIdx.x;
    const int warp = tid >> 5;
    const int lane = tid & 31;
    const int row  = lane >> 2;   // 0..7
    const int colk = lane & 3;    // 0..3
    const int wi   = warp * 16;   // warp's query-row base
    const float scale = 0.125f;

    // Load Q tile (scaled, tf32): Qs[d][i]
#pragma unroll
    for (int t = 0; t < 8; t++) {
        int v  = tid + t * 128;      // 0..1023
        int d  = v >> 4;             // 0..63
        int i4 = (v & 15) * 4;
        float4 q4 = *(const float4*)(qb + (size_t)d * NL + i0 + i4);
        Qs[d * QK_PAD + i4 + 0] = f2tf32(q4.x * scale);
        Qs[d * QK_PAD + i4 + 1] = f2tf32(q4.y * scale);
        Qs[d * QK_PAD + i4 + 2] = f2tf32(q4.z * scale);
        Qs[d * QK_PAD + i4 + 3] = f2tf32(q4.w * scale);
    }

    float m0r = -1e30f, m1r = -1e30f, l0r = 0.f, l1r = 0.f;
    float o[8][4];
#pragma unroll
    for (int df = 0; df < 8; df++)
#pragma unroll
        for (int c = 0; c < 4; c++) o[df][c] = 0.f;

    for (int jt = 0; jt < NL / 64; jt++) {
        const int j0 = jt * 64;
        __syncthreads();   // all warps done reading prior Ks/Vs
#pragma unroll
        for (int t = 0; t < 8; t++) {
            int v  = tid + t * 128;
            int d  = v >> 4;
            int j4 = (v & 15) * 4;
            float4 k4 = *(const float4*)(kb + (size_t)d * NL + j0 + j4);
            Ks[d * QK_PAD + j4 + 0] = f2tf32(k4.x);
            Ks[d * QK_PAD + j4 + 1] = f2tf32(k4.y);
            Ks[d * QK_PAD + j4 + 2] = f2tf32(k4.z);
            Ks[d * QK_PAD + j4 + 3] = f2tf32(k4.w);
            float4 v4 = *(const float4*)(vb + (size_t)d * NL + j0 + j4);
            Vs[d * PV_PAD + j4 + 0] = f2tf32(v4.x);
            Vs[d * PV_PAD + j4 + 1] = f2tf32(v4.y);
            Vs[d * PV_PAD + j4 + 2] = f2tf32(v4.z);
            Vs[d * PV_PAD + j4 + 3] = f2tf32(v4.w);
        }
        __syncthreads();

        // S = Q^T K  (m = i[16], n = j[64], k = d[64])
        float s[8][4];
#pragma unroll
        for (int jf = 0; jf < 8; jf++)
#pragma unroll
            for (int c = 0; c < 4; c++) s[jf][c] = 0.f;

#pragma unroll
        for (int ks = 0; ks < 8; ks++) {
            const int kk = ks * 8 + colk;
            uint32_t a0 = Qs[kk * QK_PAD + wi + row];
            uint32_t a1 = Qs[kk * QK_PAD + wi + row + 8];
            uint32_t a2 = Qs[(kk + 4) * QK_PAD + wi + row];
            uint32_t a3 = Qs[(kk + 4) * QK_PAD + wi + row + 8];
#pragma unroll
            for (int jf = 0; jf < 8; jf++) {
                uint32_t b0 = Ks[kk * QK_PAD + jf * 8 + row];
                uint32_t b1 = Ks[(kk + 4) * QK_PAD + jf * 8 + row];
                mma_tf32(s[jf], a0, a1, a2, a3, b0, b1);
            }
        }

        // Online softmax. Thread owns rows (wi+row) [c0,c1] and (wi+row+8) [c2,c3].
        float rm0 = -1e30f, rm1 = -1e30f;
#pragma unroll
        for (int jf = 0; jf < 8; jf++) {
            rm0 = fmaxf(rm0, fmaxf(s[jf][0], s[jf][1]));
            rm1 = fmaxf(rm1, fmaxf(s[jf][2], s[jf][3]));
        }
        rm0 = fmaxf(rm0, __shfl_xor_sync(0xffffffffu, rm0, 1, 4));
        rm0 = fmaxf(rm0, __shfl_xor_sync(0xffffffffu, rm0, 2, 4));
        rm1 = fmaxf(rm1, __shfl_xor_sync(0xffffffffu, rm1, 1, 4));
        rm1 = fmaxf(rm1, __shfl_xor_sync(0xffffffffu, rm1, 2, 4));

        float mn0 = fmaxf(m0r, rm0);
        float mn1 = fmaxf(m1r, rm1);
        float corr0 = __expf(m0r - mn0);
        float corr1 = __expf(m1r - mn1);
        m0r = mn0; m1r = mn1;

        float rs0 = 0.f, rs1 = 0.f;
#pragma unroll
        for (int jf = 0; jf < 8; jf++) {
            float p0 = __expf(s[jf][0] - mn0);
            float p1 = __expf(s[jf][1] - mn0);
            float p2 = __expf(s[jf][2] - mn1);
            float p3 = __expf(s[jf][3] - mn1);
            s[jf][0] = p0; s[jf][1] = p1; s[jf][2] = p2; s[jf][3] = p3;
            rs0 += p0 + p1;
            rs1 += p2 + p3;
        }
        rs0 += __shfl_xor_sync(0xffffffffu, rs0, 1, 4);
        rs0 += __shfl_xor_sync(0xffffffffu, rs0, 2, 4);
        rs1 += __shfl_xor_sync(0xffffffffu, rs1, 1, 4);
        rs1 += __shfl_xor_sync(0xffffffffu, rs1, 2, 4);
        l0r = l0r * corr0 + rs0;
        l1r = l1r * corr1 + rs1;

#pragma unroll
        for (int df = 0; df < 8; df++) {
            o[df][0] *= corr0; o[df][1] *= corr0;
            o[df][2] *= corr1; o[df][3] *= corr1;
        }

        // Stage P (tf32) to Ps[i][j] — warp-private rows, warp sync suffices.
#pragma unroll
        for (int jf = 0; jf < 8; jf++) {
            int jc = jf * 8 + colk * 2;
            Ps[(wi + row) * PV_PAD + jc]         = f2tf32(s[jf][0]);
            Ps[(wi + row) * PV_PAD + jc + 1]     = f2tf32(s[jf][1]);
            Ps[(wi + row + 8) * PV_PAD + jc]     = f2tf32(s[jf][2]);
            Ps[(wi + row + 8) * PV_PAD + jc + 1] = f2tf32(s[jf][3]);
        }
        __syncwarp();

        // O += P V^T  (m = i[16], n = d[64], k = j[64])
#pragma unroll
        for (int ks = 0; ks < 8; ks++) {
            const int kk = ks * 8 + colk;
            uint32_t a0 = Ps[(wi + row) * PV_PAD + kk];
            uint32_t a1 = Ps[(wi + row + 8) * PV_PAD + kk];
            uint32_t a2 = Ps[(wi + row) * PV_PAD + kk + 4];
            uint32_t a3 = Ps[(wi + row + 8) * PV_PAD + kk + 4];
#pragma unroll
            for (int df = 0; df < 8; df++) {
                uint32_t b0 = Vs[(df * 8 + row) * PV_PAD + kk];
                uint32_t b1 = Vs[(df * 8 + row) * PV_PAD + kk + 4];
                mma_tf32(o[df], a0, a1, a2, a3, b0, b1);
            }
        }
        __syncwarp();   // Ps reads done before next tile's overwrite
    }

    // Normalize, stage O[d][i] into Qs region (warp-private i-columns), write out.
    float inv0 = 1.f / l0r;
    float inv1 = 1.f / l1r;
#pragma unroll
    for (int df = 0; df < 8; df++) {
        int d = df * 8 + colk * 2;
        Qs[d * QK_PAD + wi + row]           = __float_as_uint(o[df][0] * inv0);
        Qs[(d + 1) * QK_PAD + wi + row]     = __float_as_uint(o[df][1] * inv0);
        Qs[d * QK_PAD + wi + row + 8]       = __float_as_uint(o[df][2] * inv1);
        Qs[(d + 1) * QK_PAD + wi + row + 8] = __float_as_uint(o[df][3] * inv1);
    }
    __syncthreads();

    float* ob = out + (size_t)b * HD * NL + (size_t)(h * DIM_HEAD) * NL;
#pragma unroll
    for (int t = 0; t < 8; t++) {
        int v  = tid + t * 128;
        int d  = v >> 4;
        int i4 = (v & 15) * 4;
        float4 o4;
        o4.x = __uint_as_float(Qs[d * QK_PAD + i4 + 0]);
        o4.y = __uint_as_float(Qs[d * QK_PAD + i4 + 1]);
        o4.z = __uint_as_float(Qs[d * QK_PAD + i4 + 2]);
        o4.w = __uint_as_float(Qs[d * QK_PAD + i4 + 3]);
        *(float4*)(ob + (size_t)d * NL + i0 + i4) = o4;
    }
}

// ---------------------------------------------------------------------------
// Launch
// ---------------------------------------------------------------------------
extern "C" void kernel_launch(void* const* d_in, const int* in_sizes, int n_in,
                              void* d_out, int out_size)
{
    const float* x     = (const float*)d_in[0];   // [4, 512, 2048]
    const float* w_qkv = (const float*)d_in[1];   // [512, 1536]
    const float* w_out = (const float*)d_in[2];   // [512, 512]
    const float* b_out = (const float*)d_in[3];   // [512]
    float* y = (float*)d_out;                     // [4, 512, 2048]

    float* qkv;  cudaGetSymbolAddress((void**)&qkv,  g_qkv);
    float* attn; cudaGetSymbolAddress((void**)&attn, g_attn);

    // 1) QKV projection: M=1536, N=2048, K=512
    {
        dim3 grid(NL / 128, F3 / 128, NB);
        gemm_tf32<<<grid, 256>>>(w_qkv, x, qkv, nullptr, F3, NL, NC);
    }

    // 2) Flash attention
    {
        const int smem = (2 * 64 * QK_PAD + 2 * 64 * PV_PAD) * (int)sizeof(uint32_t); // 71680
        cudaFuncSetAttribute(attn_tf32,
                             cudaFuncAttributeMaxDynamicSharedMemorySize, smem);
        dim3 grid(NL / 64, NB * HEADS);
        attn_tf32<<<grid, 128, smem>>>(attn);
    }

    // 3) Output projection + bias: M=512, N=2048, K=512
    {
        dim3 grid(NL / 128, HD / 128, NB);
        gemm_tf32<<<grid, 256>>>(w_out, attn, y, b_out, NC, NL, HD);
    }
}